// round 1
// baseline (speedup 1.0000x reference)
#include <cuda_runtime.h>
#include <math.h>

#define NPTS 8192
#define NSRC 4096
#define DIM  256
#define TILE 128
#define NT   (NPTS / TILE)          // 64 tiles per side
#define NBLK (NT * (NT + 1) / 2)    // 2080 upper-triangle tile pairs
#define KS   16
#define LDA  132                    // padded smem stride (keeps 16B alignment, spreads banks)

__device__ float  g_sq[NPTS];
__device__ double g_colsum[DIM];
__device__ double g_sumsq;
__device__ float  g_c;              // exp2 scale: -1/(16*bw'*ln2)
__device__ double g_acc;

__device__ __forceinline__ const float* row_ptr(const float* src, const float* tgt, int i) {
    return (i < NSRC) ? (src + (size_t)i * DIM) : (tgt + (size_t)(i - NSRC) * DIM);
}

// ---------------------------------------------------------------------------
__global__ void zero_kernel() {
    int t = threadIdx.x;
    if (t < DIM) g_colsum[t] = 0.0;
    if (t == 0) { g_sumsq = 0.0; g_acc = 0.0; }
}

// One warp per row: squared L2 norm of each point + global sum of norms.
__global__ void sq_kernel(const float* __restrict__ src, const float* __restrict__ tgt) {
    int gwarp = (blockIdx.x * blockDim.x + threadIdx.x) >> 5;
    int lane  = threadIdx.x & 31;
    if (gwarp >= NPTS) return;
    const float4* p4 = (const float4*)row_ptr(src, tgt, gwarp);
    float4 a = p4[lane];
    float4 b = p4[lane + 32];
    float s = a.x * a.x + a.y * a.y + a.z * a.z + a.w * a.w
            + b.x * b.x + b.y * b.y + b.z * b.z + b.w * b.w;
#pragma unroll
    for (int o = 16; o > 0; o >>= 1) s += __shfl_xor_sync(0xffffffffu, s, o);
    if (lane == 0) {
        g_sq[gwarp] = s;
        atomicAdd(&g_sumsq, (double)s);
    }
}

// Column sums of the concatenated data (for ||sum_i x_i||^2).
__global__ void colsum_kernel(const float* __restrict__ src, const float* __restrict__ tgt) {
    int t = threadIdx.x;           // column 0..255
    int r0 = blockIdx.x * 128;
    float local = 0.f;
    for (int r = 0; r < 128; r++) {
        const float* p = row_ptr(src, tgt, r0 + r);
        local += p[t];
    }
    atomicAdd(&g_colsum[t], (double)local);
}

// Compute bandwidth analytically and the exp2 scale constant.
__global__ void finalize_kernel() {
    __shared__ double red[DIM];
    int t = threadIdx.x;
    double c = g_colsum[t];
    red[t] = c * c;
    __syncthreads();
    for (int o = 128; o > 0; o >>= 1) {
        if (t < o) red[t] += red[t + o];
        __syncthreads();
    }
    if (t == 0) {
        double n = (double)NPTS;
        double sumL2 = 2.0 * n * g_sumsq - 2.0 * red[0];
        double bw = sumL2 / (n * n - n);
        bw = bw / 4.0;  // KERNEL_MUL^(KERNEL_NUM//2) = 2^2
        // u = exp(-L2/(16*bw)) = exp2(L2 * c), c = -1/(16*bw*ln2)
        g_c = (float)(-1.0 / (16.0 * bw * 0.6931471805599453));
    }
}

// ---------------------------------------------------------------------------
// Main pairwise kernel: 128x128 output tiles, symmetric (bi<=bj).
__global__ void __launch_bounds__(256, 2)
mmd_pair_kernel(const float* __restrict__ src, const float* __restrict__ tgt) {
    __shared__ float As[KS][LDA];
    __shared__ float Bs[KS][LDA];
    __shared__ float red[256];

    // Decode linear block id -> (bi, bj), bi <= bj.
    int b = blockIdx.x;
    float fb = (float)b;
    int bi = (int)((2.0f * NT + 1.0f - sqrtf((2.0f * NT + 1.0f) * (2.0f * NT + 1.0f) - 8.0f * fb)) * 0.5f);
    if (bi < 0) bi = 0;
    if (bi >= NT) bi = NT - 1;
    // start(i) = i*NT - i*(i-1)/2
#define TRI_START(i) ((i) * NT - (i) * ((i) - 1) / 2)
    while (bi + 1 < NT && TRI_START(bi + 1) <= b) bi++;
    while (bi > 0 && TRI_START(bi) > b) bi--;
    int bj = bi + (b - TRI_START(bi));
#undef TRI_START

    int row0 = bi * TILE;
    int col0 = bj * TILE;
    const float* A = row_ptr(src, tgt, row0);  // 128 rows, never crosses the src/tgt boundary
    const float* B = row_ptr(src, tgt, col0);

    int tid = threadIdx.x;
    int tx = tid & 15;
    int ty = tid >> 4;

    float acc[8][8];
#pragma unroll
    for (int i = 0; i < 8; i++)
#pragma unroll
        for (int j = 0; j < 8; j++) acc[i][j] = 0.f;

    for (int kt = 0; kt < DIM; kt += KS) {
#pragma unroll
        for (int l = 0; l < 2; l++) {
            int f = tid + l * 256;          // 0..511 float4 slots
            int r  = f >> 2;
            int c4 = (f & 3) * 4;
            float4 va = *(const float4*)(A + (size_t)r * DIM + kt + c4);
            As[c4 + 0][r] = va.x; As[c4 + 1][r] = va.y;
            As[c4 + 2][r] = va.z; As[c4 + 3][r] = va.w;
            float4 vb = *(const float4*)(B + (size_t)r * DIM + kt + c4);
            Bs[c4 + 0][r] = vb.x; Bs[c4 + 1][r] = vb.y;
            Bs[c4 + 2][r] = vb.z; Bs[c4 + 3][r] = vb.w;
        }
        __syncthreads();
#pragma unroll
        for (int kk = 0; kk < KS; kk++) {
            float a[8], bv[8];
            *(float4*)(a)      = *(const float4*)&As[kk][ty * 8];
            *(float4*)(a + 4)  = *(const float4*)&As[kk][ty * 8 + 4];
            *(float4*)(bv)     = *(const float4*)&Bs[kk][tx * 8];
            *(float4*)(bv + 4) = *(const float4*)&Bs[kk][tx * 8 + 4];
#pragma unroll
            for (int i = 0; i < 8; i++)
#pragma unroll
                for (int j = 0; j < 8; j++) acc[i][j] = fmaf(a[i], bv[j], acc[i][j]);
        }
        __syncthreads();
    }

    // Epilogue: L2 -> u = exp2(L2*c) -> u + u^2 + u^4 + u^8 + u^16
    float c = g_c;
    float sqa[8], sqb[8];
#pragma unroll
    for (int i = 0; i < 8; i++) sqa[i] = g_sq[row0 + ty * 8 + i];
#pragma unroll
    for (int j = 0; j < 8; j++) sqb[j] = g_sq[col0 + tx * 8 + j];

    float s = 0.f;
#pragma unroll
    for (int i = 0; i < 8; i++) {
#pragma unroll
        for (int j = 0; j < 8; j++) {
            float L2 = fmaxf(sqa[i] + sqb[j] - 2.f * acc[i][j], 0.f);
            float t = L2 * c;
            float u;
            asm("ex2.approx.ftz.f32 %0, %1;" : "=f"(u) : "f"(t));
            float u2 = u * u, u4 = u2 * u2, u8 = u4 * u4, u16 = u8 * u8;
            s += u + u2 + u4 + u8 + u16;
        }
    }

    red[tid] = s;
    __syncthreads();
#pragma unroll
    for (int o = 128; o > 0; o >>= 1) {
        if (tid < o) red[tid] += red[tid + o];
        __syncthreads();
    }
    if (tid == 0) {
        float w = (bi == bj) ? 1.f : 2.f;                 // off-diagonal counted twice by symmetry
        float sr = (row0 < NSRC) ? 1.f : -1.f;
        float sc = (col0 < NSRC) ? 1.f : -1.f;
        atomicAdd(&g_acc, (double)(red[0] * w * sr * sc));
    }
}

__global__ void writeout_kernel(float* out) {
    out[0] = (float)(g_acc / ((double)NSRC * (double)NSRC));
}

// ---------------------------------------------------------------------------
extern "C" void kernel_launch(void* const* d_in, const int* in_sizes, int n_in,
                              void* d_out, int out_size) {
    const float* src = (const float*)d_in[0];
    const float* tgt = (const float*)d_in[1];
    float* out = (float*)d_out;

    zero_kernel<<<1, 256>>>();
    sq_kernel<<<NPTS / 8, 256>>>(src, tgt);        // 8 warps/block -> 1024 blocks
    colsum_kernel<<<NPTS / 128, 256>>>(src, tgt);  // 64 blocks
    finalize_kernel<<<1, 256>>>();
    mmd_pair_kernel<<<NBLK, 256>>>(src, tgt);
    writeout_kernel<<<1, 1>>>(out);
}

// round 3
// speedup vs baseline: 1.9809x; 1.9809x over previous
#include <cuda_runtime.h>
#include <cuda_bf16.h>
#include <math.h>
#include <stdint.h>

#define NPTS 8192
#define NSRC 4096
#define DIM  256
#define TILE 128
#define NT   (NPTS / TILE)          // 64
#define NBLK (NT * (NT + 1) / 2)    // 2080 upper-triangle tile pairs

// ---------------------------------------------------------------- scratch
__device__ float  g_sq[NPTS];
__device__ double g_colsum[DIM];
__device__ double g_sumsq;
__device__ float  g_c;              // exp2 scale: -1/(16*bw'*ln2)
__device__ double g_acc;
__device__ __nv_bfloat16 g_hi[NPTS * DIM];
__device__ __nv_bfloat16 g_lo[NPTS * DIM];

// ---------------------------------------------------------------- helpers
__device__ __forceinline__ uint32_t smem_u32(const void* p) {
    uint32_t a;
    asm("{ .reg .u64 t; cvta.to.shared.u64 t, %1; cvt.u32.u64 %0, t; }" : "=r"(a) : "l"(p));
    return a;
}
#define CP_ASYNC16(dst, src) \
    asm volatile("cp.async.ca.shared.global [%0], [%1], 16;" :: "r"(dst), "l"(src))
#define CP_COMMIT() asm volatile("cp.async.commit_group;" ::: "memory")
#define CP_WAIT0()  asm volatile("cp.async.wait_group 0;" ::: "memory")

#define LDSM_X4(r0, r1, r2, r3, a) \
    asm volatile("ldmatrix.sync.aligned.m8n8.x4.shared.b16 {%0,%1,%2,%3}, [%4];" \
        : "=r"(r0), "=r"(r1), "=r"(r2), "=r"(r3) : "r"(a))

#define MMA_BF16(d, a, b0, b1) \
    asm volatile("mma.sync.aligned.m16n8k16.row.col.f32.bf16.bf16.f32 " \
        "{%0,%1,%2,%3}, {%4,%5,%6,%7}, {%8,%9}, {%0,%1,%2,%3};" \
        : "+f"((d)[0]), "+f"((d)[1]), "+f"((d)[2]), "+f"((d)[3]) \
        : "r"((a)[0]), "r"((a)[1]), "r"((a)[2]), "r"((a)[3]), "r"(b0), "r"(b1))

__device__ __forceinline__ const float* row_ptr(const float* src, const float* tgt, int i) {
    return (i < NSRC) ? (src + (size_t)i * DIM) : (tgt + (size_t)(i - NSRC) * DIM);
}

// ---------------------------------------------------------------- prep kernels
__global__ void zero_kernel() {
    int t = threadIdx.x;
    if (t < DIM) g_colsum[t] = 0.0;
    if (t == 0) { g_sumsq = 0.0; g_acc = 0.0; }
}

__global__ void sq_kernel(const float* __restrict__ src, const float* __restrict__ tgt) {
    int gwarp = (blockIdx.x * blockDim.x + threadIdx.x) >> 5;
    int lane  = threadIdx.x & 31;
    if (gwarp >= NPTS) return;
    const float4* p4 = (const float4*)row_ptr(src, tgt, gwarp);
    float4 a = p4[lane];
    float4 b = p4[lane + 32];
    float s = a.x * a.x + a.y * a.y + a.z * a.z + a.w * a.w
            + b.x * b.x + b.y * b.y + b.z * b.z + b.w * b.w;
#pragma unroll
    for (int o = 16; o > 0; o >>= 1) s += __shfl_xor_sync(0xffffffffu, s, o);
    if (lane == 0) {
        g_sq[gwarp] = s;
        atomicAdd(&g_sumsq, (double)s);
    }
}

__global__ void colsum_kernel(const float* __restrict__ src, const float* __restrict__ tgt) {
    int t = threadIdx.x;
    int r0 = blockIdx.x * 128;
    float local = 0.f;
    for (int r = 0; r < 128; r++) local += row_ptr(src, tgt, r0 + r)[t];
    atomicAdd(&g_colsum[t], (double)local);
}

__global__ void finalize_kernel() {
    __shared__ double red[DIM];
    int t = threadIdx.x;
    double c = g_colsum[t];
    red[t] = c * c;
    __syncthreads();
    for (int o = 128; o > 0; o >>= 1) {
        if (t < o) red[t] += red[t + o];
        __syncthreads();
    }
    if (t == 0) {
        double n = (double)NPTS;
        double sumL2 = 2.0 * n * g_sumsq - 2.0 * red[0];
        double bw = sumL2 / (n * n - n) / 4.0;   // / KERNEL_MUL^(KERNEL_NUM//2)
        g_c = (float)(-1.0 / (16.0 * bw * 0.6931471805599453));
    }
}

// fp32 -> bf16 hi/lo split
__global__ void convert_kernel(const float* __restrict__ src, const float* __restrict__ tgt) {
    int i = blockIdx.x * blockDim.x + threadIdx.x;          // float4 index
    const int half = NSRC * DIM / 4;
    float4 v = (i < half) ? ((const float4*)src)[i] : ((const float4*)tgt)[i - half];
    float x[4] = {v.x, v.y, v.z, v.w};
    uint32_t hb[4], lb[4];
#pragma unroll
    for (int k = 0; k < 4; k++) {
        __nv_bfloat16 h = __float2bfloat16_rn(x[k]);
        float r = x[k] - __bfloat162float(h);
        __nv_bfloat16 l = __float2bfloat16_rn(r);
        hb[k] = (uint32_t)__bfloat16_as_ushort(h);
        lb[k] = (uint32_t)__bfloat16_as_ushort(l);
    }
    ((uint2*)g_hi)[i] = make_uint2(hb[0] | (hb[1] << 16), hb[2] | (hb[3] << 16));
    ((uint2*)g_lo)[i] = make_uint2(lb[0] | (lb[1] << 16), lb[2] | (lb[3] << 16));
}

// ---------------------------------------------------------------- main tile kernel
// smem arrays: A_hi, A_lo, B_hi, B_lo; each 128 rows x 80B (32 bf16 + 8 pad)
#define STRIDE_B    80
#define ARR_BYTES   (128 * STRIDE_B)      // 10240
#define STAGE_BYTES (4 * ARR_BYTES)       // 40960
#define DYN_SMEM    (2 * STAGE_BYTES)     // 81920

__global__ void __launch_bounds__(256, 1)
mmd_mma_kernel() {
    extern __shared__ char dsmem[];
    __shared__ float red[256];
    __shared__ float sqa_s[TILE];
    __shared__ float sqb_s[TILE];

    uint32_t dyn_u = smem_u32(dsmem);
    int tid  = threadIdx.x;
    int wid  = tid >> 5;
    int lane = tid & 31;
    int wm   = wid & 1;       // 2 warp-rows of 64
    int wn   = wid >> 1;      // 4 warp-cols of 32

    // decode linear block id -> (bi, bj), bi <= bj
    int b = blockIdx.x;
    float fb = (float)b;
    int bi = (int)((2.0f * NT + 1.0f - sqrtf((2.0f * NT + 1.0f) * (2.0f * NT + 1.0f) - 8.0f * fb)) * 0.5f);
    if (bi < 0) bi = 0;
    if (bi >= NT) bi = NT - 1;
#define TRI_START(i) ((i) * NT - (i) * ((i) - 1) / 2)
    while (bi + 1 < NT && TRI_START(bi + 1) <= b) bi++;
    while (bi > 0 && TRI_START(bi) > b) bi--;
    int bj = bi + (b - TRI_START(bi));
#undef TRI_START
    int row0 = bi * TILE;
    int col0 = bj * TILE;

    if (tid < TILE) {
        sqa_s[tid] = g_sq[row0 + tid];
        sqb_s[tid] = g_sq[col0 + tid];
    }

    // global byte-base pointers for the 4 smem arrays
    const char* gbase[4];
    gbase[0] = (const char*)(g_hi + (size_t)row0 * DIM);
    gbase[1] = (const char*)(g_lo + (size_t)row0 * DIM);
    gbase[2] = (const char*)(g_hi + (size_t)col0 * DIM);
    gbase[3] = (const char*)(g_lo + (size_t)col0 * DIM);

    float acc[4][4][4];
#pragma unroll
    for (int mi = 0; mi < 4; mi++)
#pragma unroll
        for (int ni = 0; ni < 4; ni++)
#pragma unroll
            for (int e = 0; e < 4; e++) acc[mi][ni][e] = 0.f;

    // cp.async loader: chunk c (k = c*32..c*32+31) -> stage s
    // 2048 x 16B transfers; per thread 8; arr = i>>1 compile-time
#define ISSUE_LOADS(c, s) do { \
    _Pragma("unroll") \
    for (int i = 0; i < 8; i++) { \
        int arr = i >> 1; \
        int rem = tid + (i & 1) * 256;      /* 0..511 */ \
        int row = rem >> 2; \
        int q   = rem & 3; \
        const char* srcp = gbase[arr] + (size_t)row * 512 + (c) * 64 + q * 16; \
        uint32_t dst = dyn_u + (s) * STAGE_BYTES + arr * ARR_BYTES + row * STRIDE_B + q * 16; \
        CP_ASYNC16(dst, srcp); \
    } \
    CP_COMMIT(); \
} while (0)

    // ldmatrix lane-address components
    int a_m    = lane >> 3;                       // matrix index 0..3
    int a_rofs = ((a_m & 1) << 3) + (lane & 7);   // row within 16
    int a_koff = (a_m >> 1) << 4;                 // 0 or 16 bytes
    int b_nofs = ((a_m >> 1) << 3) + (lane & 7);  // n within 16
    int b_koff = (a_m & 1) << 4;

    ISSUE_LOADS(0, 0);
    CP_WAIT0();
    __syncthreads();

    for (int c = 0; c < 8; c++) {
        int s = c & 1;
        if (c < 7) ISSUE_LOADS(c + 1, s ^ 1);

        uint32_t stage_u = dyn_u + s * STAGE_BYTES;
#pragma unroll
        for (int ks = 0; ks < 2; ks++) {
            uint32_t Ah[4][4], Al[4][4], Bh[2][4], Bl[2][4];
#pragma unroll
            for (int mi = 0; mi < 4; mi++) {
                int r = wm * 64 + mi * 16 + a_rofs;
                uint32_t ad = stage_u + r * STRIDE_B + ks * 32 + a_koff;
                LDSM_X4(Ah[mi][0], Ah[mi][1], Ah[mi][2], Ah[mi][3], ad);
                LDSM_X4(Al[mi][0], Al[mi][1], Al[mi][2], Al[mi][3], ad + ARR_BYTES);
            }
#pragma unroll
            for (int pi = 0; pi < 2; pi++) {
                int nl = wn * 32 + pi * 16 + b_nofs;
                uint32_t bd = stage_u + 2 * ARR_BYTES + nl * STRIDE_B + ks * 32 + b_koff;
                LDSM_X4(Bh[pi][0], Bh[pi][1], Bh[pi][2], Bh[pi][3], bd);
                LDSM_X4(Bl[pi][0], Bl[pi][1], Bl[pi][2], Bl[pi][3], bd + ARR_BYTES);
            }
#pragma unroll
            for (int mi = 0; mi < 4; mi++) {
#pragma unroll
                for (int ni = 0; ni < 4; ni++) {
                    int pi = ni >> 1, h = (ni & 1) * 2;
                    MMA_BF16(acc[mi][ni], Ah[mi], Bh[pi][h], Bh[pi][h + 1]);
                    MMA_BF16(acc[mi][ni], Ah[mi], Bl[pi][h], Bl[pi][h + 1]);
                    MMA_BF16(acc[mi][ni], Al[mi], Bh[pi][h], Bh[pi][h + 1]);
                }
            }
        }
        if (c < 7) {
            CP_WAIT0();
            __syncthreads();
        }
    }

    // epilogue: fragment element (mi,ni,e): row = wm*64+mi*16 + lane/4 + (e>=2)*8
    //                                       col = wn*32+ni*8 + (lane%4)*2 + (e&1)
    float cexp = g_c;
    int rlo = lane >> 2;
    int cl0 = (lane & 3) * 2;
    float s = 0.f;
#pragma unroll
    for (int mi = 0; mi < 4; mi++) {
        float sqr0 = sqa_s[wm * 64 + mi * 16 + rlo];
        float sqr1 = sqa_s[wm * 64 + mi * 16 + rlo + 8];
#pragma unroll
        for (int ni = 0; ni < 4; ni++) {
            float sqc0 = sqb_s[wn * 32 + ni * 8 + cl0];
            float sqc1 = sqb_s[wn * 32 + ni * 8 + cl0 + 1];
#pragma unroll
            for (int e = 0; e < 4; e++) {
                float sr = (e >= 2) ? sqr1 : sqr0;
                float sc = (e & 1) ? sqc1 : sqc0;
                float L2 = fmaxf(sr + sc - 2.f * acc[mi][ni][e], 0.f);
                float u;
                asm("ex2.approx.ftz.f32 %0, %1;" : "=f"(u) : "f"(L2 * cexp));
                float u2 = u * u, u4 = u2 * u2, u8 = u4 * u4;
                s += u + u2 + u4 + u8 + u8 * u8;
            }
        }
    }

    red[tid] = s;
    __syncthreads();
#pragma unroll
    for (int o = 128; o > 0; o >>= 1) {
        if (tid < o) red[tid] += red[tid + o];
        __syncthreads();
    }
    if (tid == 0) {
        float w  = (bi == bj) ? 1.f : 2.f;
        float sr = (row0 < NSRC) ? 1.f : -1.f;
        float sc = (col0 < NSRC) ? 1.f : -1.f;
        atomicAdd(&g_acc, (double)(red[0] * w * sr * sc));
    }
}

__global__ void writeout_kernel(float* out) {
    out[0] = (float)(g_acc / ((double)NSRC * (double)NSRC));
}

// ---------------------------------------------------------------- launch
extern "C" void kernel_launch(void* const* d_in, const int* in_sizes, int n_in,
                              void* d_out, int out_size) {
    const float* src = (const float*)d_in[0];
    const float* tgt = (const float*)d_in[1];
    float* out = (float*)d_out;

    cudaFuncSetAttribute(mmd_mma_kernel, cudaFuncAttributeMaxDynamicSharedMemorySize, DYN_SMEM);

    zero_kernel<<<1, 256>>>();
    sq_kernel<<<NPTS / 8, 256>>>(src, tgt);
    colsum_kernel<<<NPTS / 128, 256>>>(src, tgt);
    finalize_kernel<<<1, 256>>>();
    convert_kernel<<<NPTS * DIM / 4 / 256, 256>>>(src, tgt);
    mmd_mma_kernel<<<NBLK, 256, DYN_SMEM>>>();
    writeout_kernel<<<1, 1>>>(out);
}

// round 4
// speedup vs baseline: 2.8460x; 1.4367x over previous
#include <cuda_runtime.h>
#include <cuda_fp16.h>
#include <math.h>
#include <stdint.h>

#define NPTS 8192
#define NSRC 4096
#define DIM  256
#define TILE 128
#define NT   (NPTS / TILE)          // 64
#define NBLK (NT * (NT + 1) / 2)    // 2080 upper-triangle tile pairs

// ---------------------------------------------------------------- scratch
__device__ float  g_sq[NPTS];
__device__ double g_colsum[DIM];
__device__ double g_sumsq;
__device__ float  g_c;              // exp2 scale: -1/(16*bw'*ln2)
__device__ double g_acc;
__device__ __half g_hi[NPTS * DIM];
__device__ __half g_lo[NPTS * DIM];

// ---------------------------------------------------------------- helpers
__device__ __forceinline__ uint32_t smem_u32(const void* p) {
    uint32_t a;
    asm("{ .reg .u64 t; cvta.to.shared.u64 t, %1; cvt.u32.u64 %0, t; }" : "=r"(a) : "l"(p));
    return a;
}
#define CP_ASYNC16(dst, src) \
    asm volatile("cp.async.ca.shared.global [%0], [%1], 16;" :: "r"(dst), "l"(src))
#define CP_COMMIT() asm volatile("cp.async.commit_group;" ::: "memory")
#define CP_WAIT1()  asm volatile("cp.async.wait_group 1;" ::: "memory")
#define CP_WAIT0()  asm volatile("cp.async.wait_group 0;" ::: "memory")

#define LDSM_X4(r0, r1, r2, r3, a) \
    asm volatile("ldmatrix.sync.aligned.m8n8.x4.shared.b16 {%0,%1,%2,%3}, [%4];" \
        : "=r"(r0), "=r"(r1), "=r"(r2), "=r"(r3) : "r"(a))

#define MMA_F16(d, a, b0, b1) \
    asm volatile("mma.sync.aligned.m16n8k16.row.col.f32.f16.f16.f32 " \
        "{%0,%1,%2,%3}, {%4,%5,%6,%7}, {%8,%9}, {%0,%1,%2,%3};" \
        : "+f"((d)[0]), "+f"((d)[1]), "+f"((d)[2]), "+f"((d)[3]) \
        : "r"((a)[0]), "r"((a)[1]), "r"((a)[2]), "r"((a)[3]), "r"(b0), "r"(b1))

__device__ __forceinline__ const float* row_ptr(const float* src, const float* tgt, int i) {
    return (i < NSRC) ? (src + (size_t)i * DIM) : (tgt + (size_t)(i - NSRC) * DIM);
}

// ---------------------------------------------------------------- prep kernels
__global__ void zero_kernel() {
    int t = threadIdx.x;
    if (t < DIM) g_colsum[t] = 0.0;
    if (t == 0) { g_sumsq = 0.0; g_acc = 0.0; }
}

// One warp per row: ||x||^2, global sum of norms, and fp16 hi/lo split.
__global__ void prep_kernel(const float* __restrict__ src, const float* __restrict__ tgt) {
    int gwarp = (blockIdx.x * blockDim.x + threadIdx.x) >> 5;
    int lane  = threadIdx.x & 31;
    if (gwarp >= NPTS) return;
    const float4* p4 = (const float4*)row_ptr(src, tgt, gwarp);
    float s = 0.f;
#pragma unroll
    for (int t = 0; t < 2; t++) {
        float4 v = p4[lane + t * 32];
        float x[4] = {v.x, v.y, v.z, v.w};
        uint32_t hb[4], lb[4];
#pragma unroll
        for (int k = 0; k < 4; k++) {
            s += x[k] * x[k];
            __half h = __float2half_rn(x[k]);
            float r = x[k] - __half2float(h);
            __half l = __float2half_rn(r);
            hb[k] = (uint32_t)__half_as_ushort(h);
            lb[k] = (uint32_t)__half_as_ushort(l);
        }
        size_t q = (size_t)gwarp * 64 + lane + t * 32;   // uint2 index (4 halves)
        ((uint2*)g_hi)[q] = make_uint2(hb[0] | (hb[1] << 16), hb[2] | (hb[3] << 16));
        ((uint2*)g_lo)[q] = make_uint2(lb[0] | (lb[1] << 16), lb[2] | (lb[3] << 16));
    }
#pragma unroll
    for (int o = 16; o > 0; o >>= 1) s += __shfl_xor_sync(0xffffffffu, s, o);
    if (lane == 0) {
        g_sq[gwarp] = s;
        atomicAdd(&g_sumsq, (double)s);
    }
}

__global__ void colsum_kernel(const float* __restrict__ src, const float* __restrict__ tgt) {
    int t = threadIdx.x;
    int r0 = blockIdx.x * 128;
    float local = 0.f;
    for (int r = 0; r < 128; r++) local += row_ptr(src, tgt, r0 + r)[t];
    atomicAdd(&g_colsum[t], (double)local);
}

__global__ void finalize_kernel() {
    __shared__ double red[DIM];
    int t = threadIdx.x;
    double c = g_colsum[t];
    red[t] = c * c;
    __syncthreads();
    for (int o = 128; o > 0; o >>= 1) {
        if (t < o) red[t] += red[t + o];
        __syncthreads();
    }
    if (t == 0) {
        double n = (double)NPTS;
        double sumL2 = 2.0 * n * g_sumsq - 2.0 * red[0];
        double bw = sumL2 / (n * n - n) / 4.0;   // / KERNEL_MUL^(KERNEL_NUM//2)
        g_c = (float)(-1.0 / (16.0 * bw * 0.6931471805599453));
    }
}

// ---------------------------------------------------------------- main tile kernel
// smem arrays per stage: A_hi, B_hi, B_lo; each 128 rows x 80B (32 fp16 + pad)
#define STRIDE_B    80
#define ARR_BYTES   (128 * STRIDE_B)      // 10240
#define STAGE_BYTES (3 * ARR_BYTES)       // 30720
#define NSTAGE      3
#define DYN_SMEM    (NSTAGE * STAGE_BYTES)  // 92160

__global__ void __launch_bounds__(256, 1)
mmd_mma_kernel() {
    extern __shared__ char dsmem[];
    __shared__ float red[256];
    __shared__ float sqa_s[TILE];
    __shared__ float sqb_s[TILE];

    uint32_t dyn_u = smem_u32(dsmem);
    int tid  = threadIdx.x;
    int wid  = tid >> 5;
    int lane = tid & 31;
    int wm   = wid & 1;       // 2 warp-rows of 64
    int wn   = wid >> 1;      // 4 warp-cols of 32

    // decode linear block id -> (bi, bj), bi <= bj
    int b = blockIdx.x;
    float fb = (float)b;
    int bi = (int)((2.0f * NT + 1.0f - sqrtf((2.0f * NT + 1.0f) * (2.0f * NT + 1.0f) - 8.0f * fb)) * 0.5f);
    if (bi < 0) bi = 0;
    if (bi >= NT) bi = NT - 1;
#define TRI_START(i) ((i) * NT - (i) * ((i) - 1) / 2)
    while (bi + 1 < NT && TRI_START(bi + 1) <= b) bi++;
    while (bi > 0 && TRI_START(bi) > b) bi--;
    int bj = bi + (b - TRI_START(bi));
#undef TRI_START
    int row0 = bi * TILE;
    int col0 = bj * TILE;

    if (tid < TILE) {
        sqa_s[tid] = g_sq[row0 + tid];
        sqb_s[tid] = g_sq[col0 + tid];
    }

    // global byte-base pointers for the 3 smem arrays
    const char* gbase[3];
    gbase[0] = (const char*)(g_hi + (size_t)row0 * DIM);   // A_hi
    gbase[1] = (const char*)(g_hi + (size_t)col0 * DIM);   // B_hi
    gbase[2] = (const char*)(g_lo + (size_t)col0 * DIM);   // B_lo

    float acc[4][4][4];
#pragma unroll
    for (int mi = 0; mi < 4; mi++)
#pragma unroll
        for (int ni = 0; ni < 4; ni++)
#pragma unroll
            for (int e = 0; e < 4; e++) acc[mi][ni][e] = 0.f;

    // loader for chunk c (k = c*32..c*32+31) into stage s: 1536 x 16B, 6/thread
#define ISSUE_LOADS(c, s) do { \
    _Pragma("unroll") \
    for (int i = 0; i < 6; i++) { \
        int arr = i >> 1; \
        int rem = tid + (i & 1) * 256;      /* 0..511 */ \
        int row = rem >> 2; \
        int q   = rem & 3; \
        const char* srcp = gbase[arr] + (size_t)row * 512 + (c) * 64 + q * 16; \
        uint32_t dst = dyn_u + (s) * STAGE_BYTES + arr * ARR_BYTES + row * STRIDE_B + q * 16; \
        CP_ASYNC16(dst, srcp); \
    } \
    CP_COMMIT(); \
} while (0)

    // ldmatrix lane-address components
    int a_m    = lane >> 3;                       // matrix index 0..3
    int a_rofs = ((a_m & 1) << 3) + (lane & 7);   // row within 16
    int a_koff = (a_m >> 1) << 4;                 // 0 or 16 bytes
    int b_nofs = ((a_m >> 1) << 3) + (lane & 7);  // n within 16
    int b_koff = (a_m & 1) << 4;

    ISSUE_LOADS(0, 0);
    ISSUE_LOADS(1, 1);

    for (int c = 0; c < 8; c++) {
        int s = c % NSTAGE;
        CP_WAIT1();                 // chunk c resident (at most chunk c+1 pending)
        __syncthreads();            // all warps past compute(c-1); stage (c+2)%3 free
        if (c + 2 < 8) ISSUE_LOADS(c + 2, (c + 2) % NSTAGE);

        uint32_t stage_u = dyn_u + s * STAGE_BYTES;
#pragma unroll
        for (int ks = 0; ks < 2; ks++) {
            uint32_t Ah[4][4], Bh[2][4], Bl[2][4];
#pragma unroll
            for (int mi = 0; mi < 4; mi++) {
                int r = wm * 64 + mi * 16 + a_rofs;
                uint32_t ad = stage_u + r * STRIDE_B + ks * 32 + a_koff;
                LDSM_X4(Ah[mi][0], Ah[mi][1], Ah[mi][2], Ah[mi][3], ad);
            }
#pragma unroll
            for (int pi = 0; pi < 2; pi++) {
                int nl = wn * 32 + pi * 16 + b_nofs;
                uint32_t bd = stage_u + ARR_BYTES + nl * STRIDE_B + ks * 32 + b_koff;
                LDSM_X4(Bh[pi][0], Bh[pi][1], Bh[pi][2], Bh[pi][3], bd);
                LDSM_X4(Bl[pi][0], Bl[pi][1], Bl[pi][2], Bl[pi][3], bd + ARR_BYTES);
            }
#pragma unroll
            for (int mi = 0; mi < 4; mi++) {
#pragma unroll
                for (int ni = 0; ni < 4; ni++) {
                    int pi = ni >> 1, h = (ni & 1) * 2;
                    MMA_F16(acc[mi][ni], Ah[mi], Bh[pi][h], Bh[pi][h + 1]);
                    MMA_F16(acc[mi][ni], Ah[mi], Bl[pi][h], Bl[pi][h + 1]);
                }
            }
        }
        __syncthreads();            // done reading stage s before it is refilled
    }

    // epilogue: fragment element (mi,ni,e): row = wm*64+mi*16 + lane/4 + (e>=2)*8
    //                                       col = wn*32+ni*8 + (lane%4)*2 + (e&1)
    float cexp = g_c;
    int rlo = lane >> 2;
    int cl0 = (lane & 3) * 2;
    float s = 0.f;
#pragma unroll
    for (int mi = 0; mi < 4; mi++) {
        float sqr0 = sqa_s[wm * 64 + mi * 16 + rlo];
        float sqr1 = sqa_s[wm * 64 + mi * 16 + rlo + 8];
#pragma unroll
        for (int ni = 0; ni < 4; ni++) {
            float sqc0 = sqb_s[wn * 32 + ni * 8 + cl0];
            float sqc1 = sqb_s[wn * 32 + ni * 8 + cl0 + 1];
#pragma unroll
            for (int e = 0; e < 4; e++) {
                float sr = (e >= 2) ? sqr1 : sqr0;
                float sc = (e & 1) ? sqc1 : sqc0;
                float L2 = fmaxf(sr + sc - 2.f * acc[mi][ni][e], 0.f);
                float u;
                asm("ex2.approx.ftz.f32 %0, %1;" : "=f"(u) : "f"(L2 * cexp));
                float u2 = u * u, u4 = u2 * u2, u8 = u4 * u4;
                s += u + u2 + u4 + u8 + u8 * u8;
            }
        }
    }

    red[tid] = s;
    __syncthreads();
#pragma unroll
    for (int o = 128; o > 0; o >>= 1) {
        if (tid < o) red[tid] += red[tid + o];
        __syncthreads();
    }
    if (tid == 0) {
        float w  = (bi == bj) ? 1.f : 2.f;
        float sr = (row0 < NSRC) ? 1.f : -1.f;
        float sc = (col0 < NSRC) ? 1.f : -1.f;
        atomicAdd(&g_acc, (double)(red[0] * w * sr * sc));
    }
}

__global__ void writeout_kernel(float* out) {
    out[0] = (float)(g_acc / ((double)NSRC * (double)NSRC));
}

// ---------------------------------------------------------------- launch
extern "C" void kernel_launch(void* const* d_in, const int* in_sizes, int n_in,
                              void* d_out, int out_size) {
    const float* src = (const float*)d_in[0];
    const float* tgt = (const float*)d_in[1];
    float* out = (float*)d_out;

    cudaFuncSetAttribute(mmd_mma_kernel, cudaFuncAttributeMaxDynamicSharedMemorySize, DYN_SMEM);

    zero_kernel<<<1, 256>>>();
    prep_kernel<<<NPTS / 8, 256>>>(src, tgt);      // sq + hi/lo split fused
    colsum_kernel<<<NPTS / 128, 256>>>(src, tgt);
    finalize_kernel<<<1, 256>>>();
    mmd_mma_kernel<<<NBLK, 256, DYN_SMEM>>>();
    writeout_kernel<<<1, 1>>>(out);
}